// round 14
// baseline (speedup 1.0000x reference)
#include <cuda_runtime.h>
#include <cuda_fp16.h>
#include <cstdint>

// ---------------- problem constants ----------------
#define BATCH 4096
#define NOBST 128
#define VEH   18
#define H     256
#define OBSF  138
#define KC    32
#define NCHUNK 8
#define NH    128          // n-half per CTA
#define LDAH  40           // halves per A row (80B pitch, ldmatrix conflict-free)
#define LDBH  40

__device__ __half g_ow2T[H * H];        // ow2 transposed [n][k], half
__device__ float  g_pooled[BATCH * H];  // encoder -> Q-head scratch

typedef unsigned long long ull;

// ---------------- encoder smem (~50 KB -> 2 CTAs/SM) ----------------
struct EncSmem {
    __half Ah[2][NOBST * LDAH];   // 2 x 10240 B : h1 chunk double-buffer (full m)
    __half Bh[2][NH * LDBH];      // 2 x 10240 B : ow2T half-chunk double-buffer
    float4 obst4[NOBST];
    float  masks[NOBST];
    float  base[H];
    float4 w4[H];
    float  ob2s[NH];              // our n-half only
    float  pooled_s[NH];
    float  veh[24];
};

// ---------------- Q-head smem ----------------
#define R2  32
#define CLD 36
struct QSmem {
    float combT[396 * CLD];
    float q1T[H * CLD];
    float wpart[8 * R2];
};

// ---------------- helpers ----------------
__device__ __forceinline__ uint32_t smaddr(const void* p) {
    return (uint32_t)__cvta_generic_to_shared(p);
}
__device__ __forceinline__ void ldsm4(uint32_t& r0, uint32_t& r1,
                                      uint32_t& r2, uint32_t& r3, uint32_t addr) {
    asm volatile("ldmatrix.sync.aligned.m8n8.x4.shared.b16 {%0,%1,%2,%3}, [%4];"
                 : "=r"(r0), "=r"(r1), "=r"(r2), "=r"(r3) : "r"(addr));
}
__device__ __forceinline__ void mma16816(float* c,
    uint32_t a0, uint32_t a1, uint32_t a2, uint32_t a3,
    uint32_t b0, uint32_t b1)
{
    asm volatile(
        "mma.sync.aligned.m16n8k16.row.col.f32.f16.f16.f32 "
        "{%0,%1,%2,%3}, {%4,%5,%6,%7}, {%8,%9}, {%0,%1,%2,%3};"
        : "+f"(c[0]), "+f"(c[1]), "+f"(c[2]), "+f"(c[3])
        : "r"(a0), "r"(a1), "r"(a2), "r"(a3), "r"(b0), "r"(b1));
}
__device__ __forceinline__ ull pack2(float x, float y) {
    ull r; asm("mov.b64 %0, {%1, %2};" : "=l"(r) : "f"(x), "f"(y)); return r;
}
__device__ __forceinline__ void unpack2(float &x, float &y, ull v) {
    asm("mov.b64 {%0, %1}, %2;" : "=f"(x), "=f"(y) : "l"(v));
}
__device__ __forceinline__ void fma2(ull &d, ull a, ull b) {
    asm("fma.rn.f32x2 %0, %1, %2, %0;" : "+l"(d) : "l"(a), "l"(b));
}

// ---------------- prep: transpose ow2 -> half [n][k] ----------------
__global__ void prep_ow2(const float* __restrict__ ow2) {
    __shared__ float tile[32][33];
    const int tx = threadIdx.x, ty = threadIdx.y;
    const int kt = blockIdx.y * 32, nt = blockIdx.x * 32;
    #pragma unroll
    for (int i = 0; i < 4; i++)
        tile[ty + 8 * i][tx] = ow2[(kt + ty + 8 * i) * H + nt + tx];
    __syncthreads();
    #pragma unroll
    for (int i = 0; i < 4; i++)
        g_ow2T[(nt + ty + 8 * i) * H + kt + tx] = __float2half(tile[tx][ty + 8 * i]);
}

// ---------------- encoder: 2 CTAs (n-halves) per batch row, 256 thr each ----------------
__device__ __forceinline__ void produce_chunk(EncSmem* S, int chunk, int buf, int t) {
    const int cl = t & 31;            // channel in chunk
    const int mg = t >> 5;            // m-group (16 rows each)
    const int c  = chunk * KC + cl;
    const float bb  = S->base[c];
    const float4 wv = S->w4[c];
    __half* dst = S->Ah[buf];
    #pragma unroll
    for (int mi = 0; mi < 16; mi++) {
        const int m = mg * 16 + mi;
        float4 o = S->obst4[m];       // warp-broadcast
        float v = fmaf(wv.x, o.x, bb);
        v = fmaf(wv.y, o.y, v);
        v = fmaf(wv.z, o.z, v);
        v = fmaf(wv.w, o.w, v);
        dst[m * LDAH + cl] = __float2half(fmaxf(v, 0.f));
    }
}

__global__ __launch_bounds__(256, 2)
void setq_enc(const float* __restrict__ obs,
              const float* __restrict__ obstacles,
              const float* __restrict__ ow1,
              const float* __restrict__ ob1,
              const float* __restrict__ ob2)
{
    extern __shared__ char smraw[];
    EncSmem* S = (EncSmem*)smraw;
    const int bc = blockIdx.x;
    const int b  = bc >> 1;          // batch row
    const int p  = bc & 1;           // n-half (0 or 1)
    const int t  = threadIdx.x;
    const int w  = t >> 5, lane = t & 31;

    // ---- stage per-batch scalars ----
    if (t < VEH) S->veh[t] = obs[b * OBSF + t];
    if (t < 128) S->masks[t] = obstacles[(b * 5 + 4) * NOBST + t];
    else { int c = t - 128; S->ob2s[c] = ob2[NH * p + c]; S->pooled_s[c] = 0.f; }
    {
        const int m = t & 127;
        #pragma unroll
        for (int j = t >> 7; j < 4; j += 2)
            ((float*)&S->obst4[m])[j] = obstacles[(b * 5 + j) * NOBST + m];
    }
    __syncthreads();

    // ---- hoisted vehicle part: thread t = channel t ----
    {
        float bb = ob1[t];
        #pragma unroll
        for (int f = 0; f < VEH; f++)
            bb = fmaf(S->veh[f], ow1[f * H + t], bb);
        S->base[t] = bb;
        S->w4[t] = make_float4(ow1[18 * H + t], ow1[19 * H + t],
                               ow1[20 * H + t], ow1[21 * H + t]);
    }
    __syncthreads();

    // ---- chunk 0: produce A, stage our B half ----
    produce_chunk(S, 0, 0, t);
    {
        const int n = t >> 1, part = t & 1;
        const __half* src = g_ow2T + (NH * p + n) * H + 0 * KC + part * 16;
        uint4 v0 = ((const uint4*)src)[0];
        uint4 v1 = ((const uint4*)src)[1];
        __half* dst = S->Bh[0] + n * LDBH + part * 16;
        ((uint4*)dst)[0] = v0;
        ((uint4*)dst)[1] = v1;
    }
    __syncthreads();

    // ---- GEMM: D[m=128][n=128 half], warp tile m32 x n64, 8 warps ----
    const int m0 = (w & 3) * 32;
    const int nq = (w >> 2) * 64;    // local n within the half

    float acc[64];
    #pragma unroll
    for (int i = 0; i < 64; i++) acc[i] = 0.f;

    const uint32_t a_lane = smaddr(S->Ah[0]) +
        (uint32_t)(((m0 + (lane & 15)) * LDAH + (lane >> 4) * 8) * 2);
    const uint32_t b_lane = smaddr(S->Bh[0]) +
        (uint32_t)(((nq + 8 * (lane >> 4) + (lane & 7)) * LDBH + ((lane >> 3) & 1) * 8) * 2);
    const uint32_t ABUF = NOBST * LDAH * 2;   // 10240 B
    const uint32_t BBUF = NH * LDBH * 2;      // 10240 B

    for (int kc = 0; kc < NCHUNK; kc++) {
        const int bi = kc & 1;
        uint4 p0, p1;
        if (kc < NCHUNK - 1) {   // prefetch next B half-chunk into regs
            const __half* src = g_ow2T + (NH * p + (t >> 1)) * H + (kc + 1) * KC + (t & 1) * 16;
            p0 = ((const uint4*)src)[0];
            p1 = ((const uint4*)src)[1];
        }
        const uint32_t aA = a_lane + bi * ABUF;
        const uint32_t aB = b_lane + bi * BBUF;
        #pragma unroll
        for (int s = 0; s < 2; s++) {
            const uint32_t koff = s * 32;
            uint32_t a0, a1, a2, a3, a4, a5, a6, a7;
            ldsm4(a0, a1, a2, a3, aA + koff);
            ldsm4(a4, a5, a6, a7, aA + 16 * LDAH * 2 + koff);
            #pragma unroll
            for (int j2 = 0; j2 < 4; j2++) {
                uint32_t b0, b1, b2, b3;
                ldsm4(b0, b1, b2, b3, aB + j2 * (16 * LDBH * 2) + koff);
                mma16816(acc + (2 * j2) * 4,          a0, a1, a2, a3, b0, b1);
                mma16816(acc + (2 * j2 + 1) * 4,      a0, a1, a2, a3, b2, b3);
                mma16816(acc + 32 + (2 * j2) * 4,     a4, a5, a6, a7, b0, b1);
                mma16816(acc + 32 + (2 * j2 + 1) * 4, a4, a5, a6, a7, b2, b3);
            }
        }
        if (kc < NCHUNK - 1) {
            const int nb = bi ^ 1;
            produce_chunk(S, kc + 1, nb, t);
            __half* dst = S->Bh[nb] + (t >> 1) * LDBH + (t & 1) * 16;
            ((uint4*)dst)[0] = p0;
            ((uint4*)dst)[1] = p1;
        }
        __syncthreads();
    }

    // ---- epilogue: bias + relu + masked pool (local n-half) ----
    {
        const int r = lane >> 2;
        const int q = lane & 3;
        const float mk0 = S->masks[m0 + r];
        const float mk1 = S->masks[m0 + r + 8];
        const float mk2 = S->masks[m0 + 16 + r];
        const float mk3 = S->masks[m0 + 24 + r];
        #pragma unroll
        for (int j = 0; j < 8; j++) {
            const int n = nq + 8 * j + 2 * q;
            const float o0 = S->ob2s[n], o1 = S->ob2s[n + 1];
            const float* c0p = acc + j * 4;
            const float* c1p = acc + 32 + j * 4;
            float v0 = mk0 * fmaxf(c0p[0] + o0, 0.f) + mk1 * fmaxf(c0p[2] + o0, 0.f)
                     + mk2 * fmaxf(c1p[0] + o0, 0.f) + mk3 * fmaxf(c1p[2] + o0, 0.f);
            float v1 = mk0 * fmaxf(c0p[1] + o1, 0.f) + mk1 * fmaxf(c0p[3] + o1, 0.f)
                     + mk2 * fmaxf(c1p[1] + o1, 0.f) + mk3 * fmaxf(c1p[3] + o1, 0.f);
            #pragma unroll
            for (int o = 4; o <= 16; o <<= 1) {
                v0 += __shfl_xor_sync(0xffffffffu, v0, o);
                v1 += __shfl_xor_sync(0xffffffffu, v1, o);
            }
            if (lane < 4) {
                atomicAdd(&S->pooled_s[nq + 8 * j + 2 * lane],     v0);
                atomicAdd(&S->pooled_s[nq + 8 * j + 2 * lane + 1], v1);
            }
        }
    }
    __syncthreads();
    if (t < NH) g_pooled[b * H + NH * p + t] = S->pooled_s[t];
}

// ---------------- Q-head: batched, exact fp32, f32x2-packed ----------------
__global__ __launch_bounds__(256, 2)
void setq_qhead(const float* __restrict__ obs,
                const float* __restrict__ act,
                const float* __restrict__ qw1,
                const float* __restrict__ qb1,
                const float* __restrict__ qw2,
                const float* __restrict__ qb2,
                const float* __restrict__ qw3,
                const float* __restrict__ qb3,
                float* __restrict__ out)
{
    extern __shared__ char smraw[];
    QSmem* S = (QSmem*)smraw;
    const int rb = blockIdx.x * R2;
    const int t  = threadIdx.x;
    const int w  = t >> 5, lane = t & 31;

    {
        const int r = t >> 3, f0 = t & 7;
        for (int f = f0; f < OBSF; f += 8)
            S->combT[f * CLD + r] = obs[(rb + r) * OBSF + f];
        for (int c = f0; c < H; c += 8)
            S->combT[(OBSF + c) * CLD + r] = g_pooled[(rb + r) * H + c];
        if (f0 < 2)
            S->combT[(OBSF + H + f0) * CLD + r] = act[(rb + r) * 2 + f0];
    }
    __syncthreads();

    const int c = t;
    ull acc1[16];
    #pragma unroll
    for (int i = 0; i < 16; i++) acc1[i] = 0ULL;
    #pragma unroll 4
    for (int k = 0; k < 396; k++) {
        const ull wp = pack2(qw1[k * H + c], qw1[k * H + c]);
        const ulonglong2* row = (const ulonglong2*)(S->combT + k * CLD);
        #pragma unroll
        for (int u = 0; u < 8; u++) {
            ulonglong2 rr = row[u];
            fma2(acc1[2 * u],     rr.x, wp);
            fma2(acc1[2 * u + 1], rr.y, wp);
        }
    }
    {
        const float bias = qb1[c];
        #pragma unroll
        for (int i = 0; i < 16; i++) {
            float x, y;
            unpack2(x, y, acc1[i]);
            S->q1T[c * CLD + 2 * i]     = fmaxf(x + bias, 0.f);
            S->q1T[c * CLD + 2 * i + 1] = fmaxf(y + bias, 0.f);
        }
    }
    __syncthreads();

    ull acc2[16];
    #pragma unroll
    for (int i = 0; i < 16; i++) acc2[i] = 0ULL;
    #pragma unroll 4
    for (int k = 0; k < H; k++) {
        const ull wp = pack2(qw2[k * H + c], qw2[k * H + c]);
        const ulonglong2* row = (const ulonglong2*)(S->q1T + k * CLD);
        #pragma unroll
        for (int u = 0; u < 8; u++) {
            ulonglong2 rr = row[u];
            fma2(acc2[2 * u],     rr.x, wp);
            fma2(acc2[2 * u + 1], rr.y, wp);
        }
    }

    {
        const float qb2c = qb2[c], qw3c = qw3[c];
        float part[R2];
        #pragma unroll
        for (int i = 0; i < 16; i++) {
            float x, y;
            unpack2(x, y, acc2[i]);
            part[2 * i]     = fmaxf(x + qb2c, 0.f) * qw3c;
            part[2 * i + 1] = fmaxf(y + qb2c, 0.f) * qw3c;
        }
        #pragma unroll
        for (int o = 16; o > 0; o >>= 1) {
            #pragma unroll
            for (int i = 0; i < R2; i++)
                part[i] += __shfl_xor_sync(0xffffffffu, part[i], o);
        }
        if (lane == 0) {
            #pragma unroll
            for (int i = 0; i < R2; i++)
                S->wpart[w * R2 + i] = part[i];
        }
    }
    __syncthreads();
    if (t < R2) {
        float s = qb3[0];
        #pragma unroll
        for (int wi = 0; wi < 8; wi++) s += S->wpart[wi * R2 + t];
        out[rb + t] = s;
    }
}

extern "C" void kernel_launch(void* const* d_in, const int* in_sizes, int n_in,
                              void* d_out, int out_size)
{
    const float* obs       = (const float*)d_in[0];
    const float* obstacles = (const float*)d_in[1];
    const float* act       = (const float*)d_in[2];
    const float* ow1       = (const float*)d_in[3];
    const float* ob1       = (const float*)d_in[4];
    const float* ow2       = (const float*)d_in[5];
    const float* ob2       = (const float*)d_in[6];
    const float* qw1       = (const float*)d_in[7];
    const float* qb1       = (const float*)d_in[8];
    const float* qw2       = (const float*)d_in[9];
    const float* qb2       = (const float*)d_in[10];
    const float* qw3       = (const float*)d_in[11];
    const float* qb3       = (const float*)d_in[12];
    float* out             = (float*)d_out;

    cudaFuncSetAttribute(setq_enc,
                         cudaFuncAttributeMaxDynamicSharedMemorySize, (int)sizeof(EncSmem));
    cudaFuncSetAttribute(setq_qhead,
                         cudaFuncAttributeMaxDynamicSharedMemorySize, (int)sizeof(QSmem));

    prep_ow2<<<dim3(8, 8), dim3(32, 8)>>>(ow2);
    setq_enc<<<BATCH * 2, 256, sizeof(EncSmem)>>>(obs, obstacles, ow1, ob1, ob2);
    setq_qhead<<<BATCH / R2, 256, sizeof(QSmem)>>>(obs, act, qw1, qb1,
                                                   qw2, qb2, qw3, qb3, out);
}

// round 16
// speedup vs baseline: 1.0085x; 1.0085x over previous
#include <cuda_runtime.h>
#include <cuda_fp16.h>
#include <cstdint>

// ---------------- problem constants ----------------
#define BATCH 4096
#define NOBST 128
#define VEH   18
#define H     256
#define OBSF  138
#define KC    32
#define NCHUNK 8
#define LDAH  40     // halves per A smem row (80B pitch: ldmatrix conflict-free)
#define LDBH  40

__device__ __half g_ow2T[H * H];        // ow2 transposed [n][k], half
__device__ float  g_pooled[BATCH * H];  // encoder -> Q-head scratch

typedef unsigned long long ull;

// ---------------- encoder smem ----------------
struct EncSmem {
    __half Ah[2][NOBST * LDAH];   // 20480 B : h1 chunk double-buffer
    __half Bh[2][H * LDBH];       // 40960 B : ow2T chunk double-buffer
    float4 obst4[NOBST];
    float  masks[NOBST];
    float  base[H];
    float4 w4[H];
    float  ob2s[H];
    float  pooled_s[H];
    float  veh[24];
};

// ---------------- Q-head smem ----------------
#define R2  32
#define CLD 36
struct QSmem {
    float combT[396 * CLD];
    float q1T[H * CLD];
    float wpart[8 * R2];
};

// ---------------- helpers ----------------
__device__ __forceinline__ uint32_t smaddr(const void* p) {
    return (uint32_t)__cvta_generic_to_shared(p);
}
__device__ __forceinline__ void ldsm4(uint32_t& r0, uint32_t& r1,
                                      uint32_t& r2, uint32_t& r3, uint32_t addr) {
    asm volatile("ldmatrix.sync.aligned.m8n8.x4.shared.b16 {%0,%1,%2,%3}, [%4];"
                 : "=r"(r0), "=r"(r1), "=r"(r2), "=r"(r3) : "r"(addr));
}
// fp16-accumulate HMMA: C/D are 2 regs (4 packed halves) — 2x rate vs f32-accum
__device__ __forceinline__ void mma16816h(uint32_t& c0, uint32_t& c1,
    uint32_t a0, uint32_t a1, uint32_t a2, uint32_t a3,
    uint32_t b0, uint32_t b1)
{
    asm volatile(
        "mma.sync.aligned.m16n8k16.row.col.f16.f16.f16.f16 "
        "{%0,%1}, {%2,%3,%4,%5}, {%6,%7}, {%0,%1};"
        : "+r"(c0), "+r"(c1)
        : "r"(a0), "r"(a1), "r"(a2), "r"(a3), "r"(b0), "r"(b1));
}
__device__ __forceinline__ ull pack2(float x, float y) {
    ull r; asm("mov.b64 %0, {%1, %2};" : "=l"(r) : "f"(x), "f"(y)); return r;
}
__device__ __forceinline__ void unpack2(float &x, float &y, ull v) {
    asm("mov.b64 {%0, %1}, %2;" : "=f"(x), "=f"(y) : "l"(v));
}
__device__ __forceinline__ void fma2(ull &d, ull a, ull b) {
    asm("fma.rn.f32x2 %0, %1, %2, %0;" : "+l"(d) : "l"(a), "l"(b));
}

// ---------------- prep: transpose ow2 -> half [n][k] ----------------
__global__ void prep_ow2(const float* __restrict__ ow2) {
    __shared__ float tile[32][33];
    const int tx = threadIdx.x, ty = threadIdx.y;
    const int kt = blockIdx.y * 32, nt = blockIdx.x * 32;
    #pragma unroll
    for (int i = 0; i < 4; i++)
        tile[ty + 8 * i][tx] = ow2[(kt + ty + 8 * i) * H + nt + tx];
    __syncthreads();
    #pragma unroll
    for (int i = 0; i < 4; i++)
        g_ow2T[(nt + ty + 8 * i) * H + kt + tx] = __float2half(tile[tx][ty + 8 * i]);
}

// ---------------- encoder: 1 CTA (512 thr) per batch row ----------------
__device__ __forceinline__ void produce_chunk(EncSmem* S, int chunk, int buf, int t) {
    const int cl = t & 31;
    const int mg = t >> 5;
    const int c  = chunk * 32 + cl;
    const float bb  = S->base[c];
    const float4 wv = S->w4[c];
    __half* dst = S->Ah[buf];
    #pragma unroll
    for (int mi = 0; mi < 8; mi++) {
        const int m = mg * 8 + mi;
        float4 o = S->obst4[m];
        float v = fmaf(wv.x, o.x, bb);
        v = fmaf(wv.y, o.y, v);
        v = fmaf(wv.z, o.z, v);
        v = fmaf(wv.w, o.w, v);
        dst[m * LDAH + cl] = __float2half(fmaxf(v, 0.f));
    }
}

__global__ __launch_bounds__(512, 1)
void setq_enc(const float* __restrict__ obs,
              const float* __restrict__ obstacles,
              const float* __restrict__ ow1,
              const float* __restrict__ ob1,
              const float* __restrict__ ob2)
{
    extern __shared__ char smraw[];
    EncSmem* S = (EncSmem*)smraw;
    const int b = blockIdx.x;
    const int t = threadIdx.x;
    const int w = t >> 5, lane = t & 31;

    // ---- stage per-batch scalars ----
    if (t < VEH) S->veh[t] = obs[b * OBSF + t];
    if (t >= 128 && t < 256) S->masks[t - 128] = obstacles[(b * 5 + 4) * NOBST + (t - 128)];
    if (t >= 256) { int c = t - 256; S->ob2s[c] = ob2[c]; S->pooled_s[c] = 0.f; }
    { int j = t >> 7, m = t & 127;
      ((float*)&S->obst4[m])[j] = obstacles[(b * 5 + j) * NOBST + m]; }
    __syncthreads();

    // ---- hoisted vehicle part per channel ----
    if (t < H) {
        float bb = ob1[t];
        #pragma unroll
        for (int f = 0; f < VEH; f++)
            bb = fmaf(S->veh[f], ow1[f * H + t], bb);
        S->base[t] = bb;
        S->w4[t] = make_float4(ow1[18 * H + t], ow1[19 * H + t],
                               ow1[20 * H + t], ow1[21 * H + t]);
    }
    __syncthreads();

    // ---- chunk 0: produce A, stage B ----
    produce_chunk(S, 0, 0, t);
    {
        const int n = t >> 1, part = t & 1;
        const __half* src = g_ow2T + n * H + 0 * KC + part * 16;
        uint4 v0 = ((const uint4*)src)[0];
        uint4 v1 = ((const uint4*)src)[1];
        __half* dst = S->Bh[0] + n * LDBH + part * 16;
        ((uint4*)dst)[0] = v0;
        ((uint4*)dst)[1] = v1;
    }
    __syncthreads();

    // ---- GEMM: D[m=128][n=256], warp tile m32 x n64, fp16-accum + chunk promote ----
    const int m0 = (w & 3) * 32;
    const int nq = (w >> 2) * 64;
    const int r  = lane >> 2;
    const int q  = lane & 3;

    float acc[64];
    #pragma unroll
    for (int i = 0; i < 64; i++) acc[i] = 0.f;

    const uint32_t a_lane = smaddr(S->Ah[0]) +
        (uint32_t)(((m0 + (lane & 15)) * LDAH + (lane >> 4) * 8) * 2);
    const uint32_t b_lane = smaddr(S->Bh[0]) +
        (uint32_t)(((nq + 8 * (lane >> 4) + (lane & 7)) * LDBH + ((lane >> 3) & 1) * 8) * 2);
    const uint32_t ABUF = NOBST * LDAH * 2;   // 10240 B
    const uint32_t BBUF = H * LDBH * 2;       // 20480 B

    for (int kc = 0; kc < NCHUNK; kc++) {
        const int bi = kc & 1;
        uint4 p0, p1;
        if (kc < NCHUNK - 1) {   // prefetch next B chunk (global, overlaps MMA)
            const __half* src = g_ow2T + (t >> 1) * H + (kc + 1) * KC + (t & 1) * 16;
            p0 = ((const uint4*)src)[0];
            p1 = ((const uint4*)src)[1];
        }
        const uint32_t aA = a_lane + bi * ABUF;
        const uint32_t aB = b_lane + bi * BBUF;

        uint32_t hacc[32];                 // fp16 accumulators for this chunk
        #pragma unroll
        for (int i = 0; i < 32; i++) hacc[i] = 0u;

        #pragma unroll
        for (int s = 0; s < 2; s++) {
            const uint32_t koff = s * 32;          // 16 halves
            uint32_t a0, a1, a2, a3, a4, a5, a6, a7;
            ldsm4(a0, a1, a2, a3, aA + koff);
            ldsm4(a4, a5, a6, a7, aA + 16 * LDAH * 2 + koff);
            #pragma unroll
            for (int j2 = 0; j2 < 4; j2++) {
                uint32_t b0, b1, b2, b3;
                ldsm4(b0, b1, b2, b3, aB + j2 * (16 * LDBH * 2) + koff);
                // n-tile (2*j2):    rows m0..m0+15 -> hacc[ (2*j2)*2 .. +1 ]
                mma16816h(hacc[(2*j2)*2],      hacc[(2*j2)*2+1],      a0,a1,a2,a3, b0,b1);
                mma16816h(hacc[(2*j2+1)*2],    hacc[(2*j2+1)*2+1],    a0,a1,a2,a3, b2,b3);
                // rows m0+16..m0+31 -> hacc[16 + ...]
                mma16816h(hacc[16+(2*j2)*2],   hacc[16+(2*j2)*2+1],   a4,a5,a6,a7, b0,b1);
                mma16816h(hacc[16+(2*j2+1)*2], hacc[16+(2*j2+1)*2+1], a4,a5,a6,a7, b2,b3);
            }
        }
        // promote chunk partials to fp32:
        //   hacc[2i]   = (row r,   cols 2q,2q+1)  -> acc[4i+0], acc[4i+1]
        //   hacc[2i+1] = (row r+8, cols 2q,2q+1)  -> acc[4i+2], acc[4i+3]
        // i=0..7: n-tiles 0..7 rows (r, r+8)      -> acc[0..31]
        // i=8..15: n-tiles 0..7 rows (r+16, r+24) -> acc[32..63]
        #pragma unroll
        for (int i = 0; i < 16; i++) {
            float2 lo = __half22float2(*(__half2*)&hacc[2 * i]);
            float2 hi = __half22float2(*(__half2*)&hacc[2 * i + 1]);
            acc[4 * i + 0] += lo.x;
            acc[4 * i + 1] += lo.y;
            acc[4 * i + 2] += hi.x;
            acc[4 * i + 3] += hi.y;
        }

        if (kc < NCHUNK - 1) {
            const int nb = bi ^ 1;
            produce_chunk(S, kc + 1, nb, t);
            __half* dst = S->Bh[nb] + (t >> 1) * LDBH + (t & 1) * 16;
            ((uint4*)dst)[0] = p0;
            ((uint4*)dst)[1] = p1;
        }
        __syncthreads();
    }

    // ---- epilogue: bias + relu + masked pool (R11 layout: j=0..7,
    //      c0p = acc + j*4 (rows r, r+8), c1p = acc + 32 + j*4 (rows r+16, r+24)) ----
    {
        const float mk0 = S->masks[m0 + r];
        const float mk1 = S->masks[m0 + r + 8];
        const float mk2 = S->masks[m0 + 16 + r];
        const float mk3 = S->masks[m0 + 24 + r];
        #pragma unroll
        for (int j = 0; j < 8; j++) {
            const int n = nq + 8 * j + 2 * q;
            const float o0 = S->ob2s[n], o1 = S->ob2s[n + 1];
            const float* c0p = acc + j * 4;
            const float* c1p = acc + 32 + j * 4;
            float v0 = mk0 * fmaxf(c0p[0] + o0, 0.f) + mk1 * fmaxf(c0p[2] + o0, 0.f)
                     + mk2 * fmaxf(c1p[0] + o0, 0.f) + mk3 * fmaxf(c1p[2] + o0, 0.f);
            float v1 = mk0 * fmaxf(c0p[1] + o1, 0.f) + mk1 * fmaxf(c0p[3] + o1, 0.f)
                     + mk2 * fmaxf(c1p[1] + o1, 0.f) + mk3 * fmaxf(c1p[3] + o1, 0.f);
            #pragma unroll
            for (int o = 4; o <= 16; o <<= 1) {
                v0 += __shfl_xor_sync(0xffffffffu, v0, o);
                v1 += __shfl_xor_sync(0xffffffffu, v1, o);
            }
            if (lane < 4) {
                atomicAdd(&S->pooled_s[nq + 8 * j + 2 * lane],     v0);
                atomicAdd(&S->pooled_s[nq + 8 * j + 2 * lane + 1], v1);
            }
        }
    }
    __syncthreads();
    if (t < H) g_pooled[b * H + t] = S->pooled_s[t];
}

// ---------------- Q-head: batched, exact fp32, f32x2-packed ----------------
__global__ __launch_bounds__(256, 2)
void setq_qhead(const float* __restrict__ obs,
                const float* __restrict__ act,
                const float* __restrict__ qw1,
                const float* __restrict__ qb1,
                const float* __restrict__ qw2,
                const float* __restrict__ qb2,
                const float* __restrict__ qw3,
                const float* __restrict__ qb3,
                float* __restrict__ out)
{
    extern __shared__ char smraw[];
    QSmem* S = (QSmem*)smraw;
    const int rb = blockIdx.x * R2;
    const int t  = threadIdx.x;
    const int w  = t >> 5, lane = t & 31;

    {
        const int r = t >> 3, f0 = t & 7;
        for (int f = f0; f < OBSF; f += 8)
            S->combT[f * CLD + r] = obs[(rb + r) * OBSF + f];
        for (int c = f0; c < H; c += 8)
            S->combT[(OBSF + c) * CLD + r] = g_pooled[(rb + r) * H + c];
        if (f0 < 2)
            S->combT[(OBSF + H + f0) * CLD + r] = act[(rb + r) * 2 + f0];
    }
    __syncthreads();

    const int c = t;
    ull acc1[16];
    #pragma unroll
    for (int i = 0; i < 16; i++) acc1[i] = 0ULL;
    #pragma unroll 4
    for (int k = 0; k < 396; k++) {
        const ull wp = pack2(qw1[k * H + c], qw1[k * H + c]);
        const ulonglong2* row = (const ulonglong2*)(S->combT + k * CLD);
        #pragma unroll
        for (int u = 0; u < 8; u++) {
            ulonglong2 rr = row[u];
            fma2(acc1[2 * u],     rr.x, wp);
            fma2(acc1[2 * u + 1], rr.y, wp);
        }
    }
    {
        const float bias = qb1[c];
        #pragma unroll
        for (int i = 0; i < 16; i++) {
            float x, y;
            unpack2(x, y, acc1[i]);
            S->q1T[c * CLD + 2 * i]     = fmaxf(x + bias, 0.f);
            S->q1T[c * CLD + 2 * i + 1] = fmaxf(y + bias, 0.f);
        }
    }
    __syncthreads();

    ull acc2[16];
    #pragma unroll
    for (int i = 0; i < 16; i++) acc2[i] = 0ULL;
    #pragma unroll 4
    for (int k = 0; k < H; k++) {
        const ull wp = pack2(qw2[k * H + c], qw2[k * H + c]);
        const ulonglong2* row = (const ulonglong2*)(S->q1T + k * CLD);
        #pragma unroll
        for (int u = 0; u < 8; u++) {
            ulonglong2 rr = row[u];
            fma2(acc2[2 * u],     rr.x, wp);
            fma2(acc2[2 * u + 1], rr.y, wp);
        }
    }

    {
        const float qb2c = qb2[c], qw3c = qw3[c];
        float part[R2];
        #pragma unroll
        for (int i = 0; i < 16; i++) {
            float x, y;
            unpack2(x, y, acc2[i]);
            part[2 * i]     = fmaxf(x + qb2c, 0.f) * qw3c;
            part[2 * i + 1] = fmaxf(y + qb2c, 0.f) * qw3c;
        }
        #pragma unroll
        for (int o = 16; o > 0; o >>= 1) {
            #pragma unroll
            for (int i = 0; i < R2; i++)
                part[i] += __shfl_xor_sync(0xffffffffu, part[i], o);
        }
        if (lane == 0) {
            #pragma unroll
            for (int i = 0; i < R2; i++)
                S->wpart[w * R2 + i] = part[i];
        }
    }
    __syncthreads();
    if (t < R2) {
        float s = qb3[0];
        #pragma unroll
        for (int wi = 0; wi < 8; wi++) s += S->wpart[wi * R2 + t];
        out[rb + t] = s;
    }
}

extern "C" void kernel_launch(void* const* d_in, const int* in_sizes, int n_in,
                              void* d_out, int out_size)
{
    const float* obs       = (const float*)d_in[0];
    const float* obstacles = (const float*)d_in[1];
    const float* act       = (const float*)d_in[2];
    const float* ow1       = (const float*)d_in[3];
    const float* ob1       = (const float*)d_in[4];
    const float* ow2       = (const float*)d_in[5];
    const float* ob2       = (const float*)d_in[6];
    const float* qw1       = (const float*)d_in[7];
    const float* qb1       = (const float*)d_in[8];
    const float* qw2       = (const float*)d_in[9];
    const float* qb2       = (const float*)d_in[10];
    const float* qw3       = (const float*)d_in[11];
    const float* qb3       = (const float*)d_in[12];
    float* out             = (float*)d_out;

    cudaFuncSetAttribute(setq_enc,
                         cudaFuncAttributeMaxDynamicSharedMemorySize, (int)sizeof(EncSmem));
    cudaFuncSetAttribute(setq_qhead,
                         cudaFuncAttributeMaxDynamicSharedMemorySize, (int)sizeof(QSmem));

    prep_ow2<<<dim3(8, 8), dim3(32, 8)>>>(ow2);
    setq_enc<<<BATCH, 512, sizeof(EncSmem)>>>(obs, obstacles, ow1, ob1, ob2);
    setq_qhead<<<BATCH / R2, 256, sizeof(QSmem)>>>(obs, act, qw1, qb1,
                                                   qw2, qb2, qw3, qb3, out);
}

// round 17
// speedup vs baseline: 1.4783x; 1.4658x over previous
#include <cuda_runtime.h>
#include <cuda_fp16.h>
#include <cstdint>

// ---------------- problem constants ----------------
#define BATCH 4096
#define NOBST 128
#define VEH   18
#define H     256
#define OBSF  138
#define GRID  148          // persistent: 1 CTA/SM
#define LDA   264          // halves per A row (528B pitch, ldmatrix conflict-free)
#define LDB   264

__device__ __half g_ow2T[H * H];        // ow2 transposed [n][k], half
__device__ float  g_pooled[BATCH * H];  // encoder -> Q-head scratch

typedef unsigned long long ull;

// ---------------- encoder smem (~212.5 KB, persistent B + full A) ----------------
struct EncSmem {
    __half A[NOBST * LDA];        // 67584 B : h1 full tile [m][k]
    __half B[H * LDB];            // 135168 B: ow2T resident [n][k]
    float4 obst4[NOBST];
    float  masks[NOBST];
    float  base[H];
    float4 w4[H];
    float  ob2s[H];
    float  pooled_s[H];
};

// ---------------- Q-head smem ----------------
#define R2  32
#define CLD 36
struct QSmem {
    float combT[396 * CLD];
    float q1T[H * CLD];
    float wpart[8 * R2];
};

// ---------------- helpers ----------------
__device__ __forceinline__ uint32_t smaddr(const void* p) {
    return (uint32_t)__cvta_generic_to_shared(p);
}
__device__ __forceinline__ void ldsm4(uint32_t& r0, uint32_t& r1,
                                      uint32_t& r2, uint32_t& r3, uint32_t addr) {
    asm volatile("ldmatrix.sync.aligned.m8n8.x4.shared.b16 {%0,%1,%2,%3}, [%4];"
                 : "=r"(r0), "=r"(r1), "=r"(r2), "=r"(r3) : "r"(addr));
}
__device__ __forceinline__ void mma16816(float* c,
    uint32_t a0, uint32_t a1, uint32_t a2, uint32_t a3,
    uint32_t b0, uint32_t b1)
{
    asm volatile(
        "mma.sync.aligned.m16n8k16.row.col.f32.f16.f16.f32 "
        "{%0,%1,%2,%3}, {%4,%5,%6,%7}, {%8,%9}, {%0,%1,%2,%3};"
        : "+f"(c[0]), "+f"(c[1]), "+f"(c[2]), "+f"(c[3])
        : "r"(a0), "r"(a1), "r"(a2), "r"(a3), "r"(b0), "r"(b1));
}
__device__ __forceinline__ ull pack2(float x, float y) {
    ull r; asm("mov.b64 %0, {%1, %2};" : "=l"(r) : "f"(x), "f"(y)); return r;
}
__device__ __forceinline__ void unpack2(float &x, float &y, ull v) {
    asm("mov.b64 {%0, %1}, %2;" : "=f"(x), "=f"(y) : "l"(v));
}
__device__ __forceinline__ void fma2(ull &d, ull a, ull b) {
    asm("fma.rn.f32x2 %0, %1, %2, %0;" : "+l"(d) : "l"(a), "l"(b));
}

// ---------------- prep: transpose ow2 -> half [n][k] ----------------
__global__ void prep_ow2(const float* __restrict__ ow2) {
    __shared__ float tile[32][33];
    const int tx = threadIdx.x, ty = threadIdx.y;
    const int kt = blockIdx.y * 32, nt = blockIdx.x * 32;
    #pragma unroll
    for (int i = 0; i < 4; i++)
        tile[ty + 8 * i][tx] = ow2[(kt + ty + 8 * i) * H + nt + tx];
    __syncthreads();
    #pragma unroll
    for (int i = 0; i < 4; i++)
        g_ow2T[(nt + ty + 8 * i) * H + kt + tx] = __float2half(tile[tx][ty + 8 * i]);
}

// ---------------- produce full A: h1[m][k] for one batch row ----------------
__device__ __forceinline__ void produce_A(EncSmem* S, int t) {
    const int c0 = (t & 127) * 2;        // channel pair
    const int mg = t >> 7;               // m-group (32 rows each)
    const float b0v = S->base[c0],  b1v = S->base[c0 + 1];
    const float4 w0 = S->w4[c0];
    const float4 w1 = S->w4[c0 + 1];
    #pragma unroll 4
    for (int mi = 0; mi < 32; mi++) {
        const int m = mg * 32 + mi;
        float4 o = S->obst4[m];
        float v0 = b0v, v1 = b1v;
        v0 = fmaf(w0.x, o.x, v0);  v1 = fmaf(w1.x, o.x, v1);
        v0 = fmaf(w0.y, o.y, v0);  v1 = fmaf(w1.y, o.y, v1);
        v0 = fmaf(w0.z, o.z, v0);  v1 = fmaf(w1.z, o.z, v1);
        v0 = fmaf(w0.w, o.w, v0);  v1 = fmaf(w1.w, o.w, v1);
        *(__half2*)(S->A + m * LDA + c0) =
            __floats2half2_rn(fmaxf(v0, 0.f), fmaxf(v1, 0.f));
    }
}

// ---------------- encoder: persistent, ~28 rows per CTA ----------------
__global__ __launch_bounds__(512, 1)
void setq_enc(const float* __restrict__ obs,
              const float* __restrict__ obstacles,
              const float* __restrict__ ow1,
              const float* __restrict__ ob1,
              const float* __restrict__ ob2)
{
    extern __shared__ char smraw[];
    EncSmem* S = (EncSmem*)smraw;
    const int t = threadIdx.x;
    const int w = t >> 5, lane = t & 31;

    // ---- once per CTA: stage full B, w4, ob2s, zero pooled ----
    {
        const int n = t >> 1, part = t & 1;
        const uint4* src = (const uint4*)(g_ow2T + n * H + part * 128);
        uint4* dst = (uint4*)(S->B + n * LDB + part * 128);
        #pragma unroll
        for (int i = 0; i < 16; i++) dst[i] = src[i];
    }
    if (t < H) {
        S->w4[t] = make_float4(ow1[18 * H + t], ow1[19 * H + t],
                               ow1[20 * H + t], ow1[21 * H + t]);
        S->ob2s[t]    = ob2[t];
        S->pooled_s[t] = 0.f;
    }

    // ---- prologue: first row's base / obst / masks ----
    int b = blockIdx.x;
    if (t < H) {
        float bb = ob1[t];
        #pragma unroll
        for (int f = 0; f < VEH; f++)
            bb = fmaf(obs[b * OBSF + f], ow1[f * H + t], bb);
        S->base[t] = bb;
    }
    { int j = t >> 7, m = t & 127;
      ((float*)&S->obst4[m])[j] = obstacles[(b * 5 + j) * NOBST + m]; }
    if (t < 128) S->masks[t] = obstacles[(b * 5 + 4) * NOBST + t];
    __syncthreads();

    produce_A(S, t);
    __syncthreads();

    const int m0 = (w & 3) * 32;
    const int nq = (w >> 2) * 64;
    const int r  = lane >> 2;
    const int q  = lane & 3;
    const uint32_t aA = smaddr(S->A) +
        (uint32_t)(((m0 + (lane & 15)) * LDA + (lane >> 4) * 8) * 2);
    const uint32_t aB = smaddr(S->B) +
        (uint32_t)(((nq + 8 * (lane >> 4) + (lane & 7)) * LDB + ((lane >> 3) & 1) * 8) * 2);

    for (;;) {
        const int bn = b + GRID;
        // masks for this row -> regs (written last epilogue phase; barrier since)
        const float mk0 = S->masks[m0 + r];
        const float mk1 = S->masks[m0 + r + 8];
        const float mk2 = S->masks[m0 + 16 + r];
        const float mk3 = S->masks[m0 + 24 + r];

        // ---- MMA: 256 HMMA per warp over resident A/B, no barriers ----
        float acc[64];
        #pragma unroll
        for (int i = 0; i < 64; i++) acc[i] = 0.f;

        #pragma unroll 4
        for (int ks = 0; ks < 16; ks++) {
            const uint32_t koff = ks * 32;       // 16 halves
            uint32_t a0, a1, a2, a3, a4, a5, a6, a7;
            ldsm4(a0, a1, a2, a3, aA + koff);
            ldsm4(a4, a5, a6, a7, aA + 16 * LDA * 2 + koff);
            #pragma unroll
            for (int j2 = 0; j2 < 4; j2++) {
                uint32_t b0, b1, b2, b3;
                ldsm4(b0, b1, b2, b3, aB + j2 * (16 * LDB * 2) + koff);
                mma16816(acc + (2 * j2) * 4,          a0, a1, a2, a3, b0, b1);
                mma16816(acc + (2 * j2 + 1) * 4,      a0, a1, a2, a3, b2, b3);
                mma16816(acc + 32 + (2 * j2) * 4,     a4, a5, a6, a7, b0, b1);
                mma16816(acc + 32 + (2 * j2 + 1) * 4, a4, a5, a6, a7, b2, b3);
            }
        }
        __syncthreads();     // MMA done reading A; pooled_s zeroed

        // ---- epilogue: bias + relu + masked pool (atomics into pooled_s) ----
        #pragma unroll
        for (int j = 0; j < 8; j++) {
            const int n = nq + 8 * j + 2 * q;
            const float o0 = S->ob2s[n], o1 = S->ob2s[n + 1];
            const float* c0p = acc + j * 4;
            const float* c1p = acc + 32 + j * 4;
            float v0 = mk0 * fmaxf(c0p[0] + o0, 0.f) + mk1 * fmaxf(c0p[2] + o0, 0.f)
                     + mk2 * fmaxf(c1p[0] + o0, 0.f) + mk3 * fmaxf(c1p[2] + o0, 0.f);
            float v1 = mk0 * fmaxf(c0p[1] + o1, 0.f) + mk1 * fmaxf(c0p[3] + o1, 0.f)
                     + mk2 * fmaxf(c1p[1] + o1, 0.f) + mk3 * fmaxf(c1p[3] + o1, 0.f);
            #pragma unroll
            for (int o = 4; o <= 16; o <<= 1) {
                v0 += __shfl_xor_sync(0xffffffffu, v0, o);
                v1 += __shfl_xor_sync(0xffffffffu, v1, o);
            }
            if (lane < 4) {
                atomicAdd(&S->pooled_s[nq + 8 * j + 2 * lane],     v0);
                atomicAdd(&S->pooled_s[nq + 8 * j + 2 * lane + 1], v1);
            }
        }

        // ---- prep next row (same phase; masks/obst/base safe to overwrite) ----
        if (bn < BATCH) {
            if (t < H) {
                float bb = ob1[t];
                #pragma unroll
                for (int f = 0; f < VEH; f++)
                    bb = fmaf(obs[bn * OBSF + f], ow1[f * H + t], bb);
                S->base[t] = bb;
            }
            { int j = t >> 7, m = t & 127;
              ((float*)&S->obst4[m])[j] = obstacles[(bn * 5 + j) * NOBST + m]; }
            if (t < 128) S->masks[t] = obstacles[(bn * 5 + 4) * NOBST + t];
        }
        __syncthreads();     // atomics complete; next-row smem visible

        if (t < H) {
            g_pooled[b * H + t] = S->pooled_s[t];
            S->pooled_s[t] = 0.f;
        }
        b = bn;
        if (b >= BATCH) break;
        produce_A(S, t);
        __syncthreads();     // A + pooled reset visible
    }
}

// ---------------- Q-head: batched, exact fp32, f32x2-packed ----------------
__global__ __launch_bounds__(256, 2)
void setq_qhead(const float* __restrict__ obs,
                const float* __restrict__ act,
                const float* __restrict__ qw1,
                const float* __restrict__ qb1,
                const float* __restrict__ qw2,
                const float* __restrict__ qb2,
                const float* __restrict__ qw3,
                const float* __restrict__ qb3,
                float* __restrict__ out)
{
    extern __shared__ char smraw[];
    QSmem* S = (QSmem*)smraw;
    const int rb = blockIdx.x * R2;
    const int t  = threadIdx.x;
    const int w  = t >> 5, lane = t & 31;

    {
        const int r = t >> 3, f0 = t & 7;
        for (int f = f0; f < OBSF; f += 8)
            S->combT[f * CLD + r] = obs[(rb + r) * OBSF + f];
        for (int c = f0; c < H; c += 8)
            S->combT[(OBSF + c) * CLD + r] = g_pooled[(rb + r) * H + c];
        if (f0 < 2)
            S->combT[(OBSF + H + f0) * CLD + r] = act[(rb + r) * 2 + f0];
    }
    __syncthreads();

    const int c = t;
    ull acc1[16];
    #pragma unroll
    for (int i = 0; i < 16; i++) acc1[i] = 0ULL;
    #pragma unroll 4
    for (int k = 0; k < 396; k++) {
        const ull wp = pack2(qw1[k * H + c], qw1[k * H + c]);
        const ulonglong2* row = (const ulonglong2*)(S->combT + k * CLD);
        #pragma unroll
        for (int u = 0; u < 8; u++) {
            ulonglong2 rr = row[u];
            fma2(acc1[2 * u],     rr.x, wp);
            fma2(acc1[2 * u + 1], rr.y, wp);
        }
    }
    {
        const float bias = qb1[c];
        #pragma unroll
        for (int i = 0; i < 16; i++) {
            float x, y;
            unpack2(x, y, acc1[i]);
            S->q1T[c * CLD + 2 * i]     = fmaxf(x + bias, 0.f);
            S->q1T[c * CLD + 2 * i + 1] = fmaxf(y + bias, 0.f);
        }
    }
    __syncthreads();

    ull acc2[16];
    #pragma unroll
    for (int i = 0; i < 16; i++) acc2[i] = 0ULL;
    #pragma unroll 4
    for (int k = 0; k < H; k++) {
        const ull wp = pack2(qw2[k * H + c], qw2[k * H + c]);
        const ulonglong2* row = (const ulonglong2*)(S->q1T + k * CLD);
        #pragma unroll
        for (int u = 0; u < 8; u++) {
            ulonglong2 rr = row[u];
            fma2(acc2[2 * u],     rr.x, wp);
            fma2(acc2[2 * u + 1], rr.y, wp);
        }
    }

    {
        const float qb2c = qb2[c], qw3c = qw3[c];
        float part[R2];
        #pragma unroll
        for (int i = 0; i < 16; i++) {
            float x, y;
            unpack2(x, y, acc2[i]);
            part[2 * i]     = fmaxf(x + qb2c, 0.f) * qw3c;
            part[2 * i + 1] = fmaxf(y + qb2c, 0.f) * qw3c;
        }
        #pragma unroll
        for (int o = 16; o > 0; o >>= 1) {
            #pragma unroll
            for (int i = 0; i < R2; i++)
                part[i] += __shfl_xor_sync(0xffffffffu, part[i], o);
        }
        if (lane == 0) {
            #pragma unroll
            for (int i = 0; i < R2; i++)
                S->wpart[w * R2 + i] = part[i];
        }
    }
    __syncthreads();
    if (t < R2) {
        float s = qb3[0];
        #pragma unroll
        for (int wi = 0; wi < 8; wi++) s += S->wpart[wi * R2 + t];
        out[rb + t] = s;
    }
}

extern "C" void kernel_launch(void* const* d_in, const int* in_sizes, int n_in,
                              void* d_out, int out_size)
{
    const float* obs       = (const float*)d_in[0];
    const float* obstacles = (const float*)d_in[1];
    const float* act       = (const float*)d_in[2];
    const float* ow1       = (const float*)d_in[3];
    const float* ob1       = (const float*)d_in[4];
    const float* ow2       = (const float*)d_in[5];
    const float* ob2       = (const float*)d_in[6];
    const float* qw1       = (const float*)d_in[7];
    const float* qb1       = (const float*)d_in[8];
    const float* qw2       = (const float*)d_in[9];
    const float* qb2       = (const float*)d_in[10];
    const float* qw3       = (const float*)d_in[11];
    const float* qb3       = (const float*)d_in[12];
    float* out             = (float*)d_out;

    cudaFuncSetAttribute(setq_enc,
                         cudaFuncAttributeMaxDynamicSharedMemorySize, (int)sizeof(EncSmem));
    cudaFuncSetAttribute(setq_qhead,
                         cudaFuncAttributeMaxDynamicSharedMemorySize, (int)sizeof(QSmem));

    prep_ow2<<<dim3(8, 8), dim3(32, 8)>>>(ow2);
    setq_enc<<<GRID, 512, sizeof(EncSmem)>>>(obs, obstacles, ow1, ob1, ob2);
    setq_qhead<<<BATCH / R2, 256, sizeof(QSmem)>>>(obs, act, qw1, qb1,
                                                   qw2, qb2, qw3, qb3, out);
}